// round 9
// baseline (speedup 1.0000x reference)
#include <cuda_runtime.h>
#include <math.h>

#define NN 50000
#define EE 400000
#define FF 32
#define HALF_E (EE / 2)

typedef unsigned long long ull;

// ---------------- scratch ----------------
__device__ __align__(128) float g_e1[(size_t)EE * FF];
__device__ __align__(128) float g_e2[(size_t)EE * FF];
__device__ __align__(128) float g_e3[(size_t)EE * FF];
__device__ __align__(128) float g_acc1[(size_t)NN * FF];
__device__ __align__(128) float g_acc2[(size_t)NN * FF];
__device__ __align__(128) float g_acc3[(size_t)NN * FF];
__device__ __align__(128) float g_uv[(size_t)NN * 64];
__device__ __align__(128) float g_cnt[NN];
__device__ __align__(16) float g_wx[FF * 4];
__device__ __align__(16) float g_bx[4];
__device__ __align__(16) float g_wz[FF];
__device__ float g_bz;

// ---------------- f32x2 helpers ----------------
__device__ __forceinline__ void ffma2(ull& d, ull a, ull b) {
    asm("fma.rn.f32x2 %0, %1, %2, %0;" : "+l"(d) : "l"(a), "l"(b));
}
__device__ __forceinline__ ull pk2(float v) {
    ull r;
    asm("mov.b64 %0, {%1, %1};" : "=l"(r) : "f"(v));
    return r;
}
union V32 {
    float f[FF];
    ull u[FF / 2];
};
union V16 {
    float f[16];
    ull u[8];
};

__device__ __forceinline__ void cpsh(float* dst, const float* src, int n, int tid, int nt) {
    for (int i = tid; i < n; i += nt) dst[i] = src[i];
}
__device__ __forceinline__ void ldbias(V32& h, const float* __restrict__ b) {
#pragma unroll
    for (int j = 0; j < FF; j++) h.f[j] = b[j];
}
__device__ __forceinline__ void relu32(V32& h) {
#pragma unroll
    for (int j = 0; j < FF; j++) h.f[j] = fmaxf(h.f[j], 0.f);
}
__device__ __forceinline__ void red4(float* __restrict__ a, float x, float y, float z, float w) {
    asm volatile("red.global.add.v4.f32 [%0], {%1, %2, %3, %4};" ::"l"(a), "f"(x), "f"(y),
                 "f"(z), "f"(w)
                 : "memory");
}
__device__ __forceinline__ void scatter16(float* __restrict__ acc, const V16& o) {
    red4(acc, o.f[0], o.f[1], o.f[2], o.f[3]);
    red4(acc + 4, o.f[4], o.f[5], o.f[6], o.f[7]);
    red4(acc + 8, o.f[8], o.f[9], o.f[10], o.f[11]);
    red4(acc + 12, o.f[12], o.f[13], o.f[14], o.f[15]);
}
__device__ __forceinline__ void store_relu16(float* __restrict__ dst, const V16& o) {
#pragma unroll
    for (int j = 0; j < 16; j += 4)
        *(float4*)(dst + j) = make_float4(fmaxf(o.f[j], 0.f), fmaxf(o.f[j + 1], 0.f),
                                          fmaxf(o.f[j + 2], 0.f), fmaxf(o.f[j + 3], 0.f));
}

__device__ __forceinline__ void fmarow2p(V32& h0, V32& h1, ull v0, ull v1,
                                         const float* __restrict__ wr) {
#pragma unroll
    for (int j = 0; j < 8; j++) {
        ulonglong2 w = *(const ulonglong2*)(wr + j * 4);
        ffma2(h0.u[2 * j + 0], v0, w.x);
        ffma2(h0.u[2 * j + 1], v0, w.y);
        ffma2(h1.u[2 * j + 0], v1, w.x);
        ffma2(h1.u[2 * j + 1], v1, w.y);
    }
}
__device__ __forceinline__ void seg32p(V32& h0, V32& h1, const float* __restrict__ s0,
                                       const float* __restrict__ s1,
                                       const float* __restrict__ ws) {
#pragma unroll
    for (int k = 0; k < FF; k += 4) {
        float4 a = *(const float4*)(s0 + k);
        float4 b = *(const float4*)(s1 + k);
        fmarow2p(h0, h1, pk2(a.x), pk2(b.x), ws + (k + 0) * FF);
        fmarow2p(h0, h1, pk2(a.y), pk2(b.y), ws + (k + 1) * FF);
        fmarow2p(h0, h1, pk2(a.z), pk2(b.z), ws + (k + 2) * FF);
        fmarow2p(h0, h1, pk2(a.w), pk2(b.w), ws + (k + 3) * FF);
    }
}
// full second layer (edge4 only)
__device__ __forceinline__ void layer2p(V32& o0, V32& o1, const V32& h0, const V32& h1,
                                        const float* __restrict__ sw1,
                                        const float* __restrict__ sb1) {
    ldbias(o0, sb1);
    ldbias(o1, sb1);
#pragma unroll
    for (int k = 0; k < FF; k++) fmarow2p(o0, o1, pk2(h0.f[k]), pk2(h1.f[k]), sw1 + k * FF);
}
// half (16-col) second layer for a pair
__device__ __forceinline__ void layer2ph(V16& o0, V16& o1, const V32& h0, const V32& h1,
                                         const float* __restrict__ sw1,
                                         const float* __restrict__ sb1, int hf) {
    const float* sb = sb1 + hf * 16;
#pragma unroll
    for (int j = 0; j < 16; j++) {
        o0.f[j] = sb[j];
        o1.f[j] = sb[j];
    }
#pragma unroll
    for (int k = 0; k < FF; k++) {
        const float* wr = sw1 + k * FF + hf * 16;
        ull v0 = pk2(h0.f[k]), v1 = pk2(h1.f[k]);
#pragma unroll
        for (int j = 0; j < 4; j++) {
            ulonglong2 w = *(const ulonglong2*)(wr + j * 4);
            ffma2(o0.u[2 * j + 0], v0, w.x);
            ffma2(o0.u[2 * j + 1], v0, w.y);
            ffma2(o1.u[2 * j + 0], v1, w.x);
            ffma2(o1.u[2 * j + 1], v1, w.y);
        }
    }
}
__device__ __forceinline__ void uvinit(V32& h, int r, int c) {
    const float* U = g_uv + (size_t)r * 64;
    const float* V = g_uv + (size_t)c * 64 + 32;
#pragma unroll
    for (int j = 0; j < FF; j += 4) {
        float4 a = *(const float4*)(U + j);
        float4 b = *(const float4*)(V + j);
        h.f[j + 0] = a.x + b.x;
        h.f[j + 1] = a.y + b.y;
        h.f[j + 2] = a.z + b.z;
        h.f[j + 3] = a.w + b.w;
    }
}

// ---------------- init / head fold ----------------
__global__ void k_init(const float* __restrict__ beta, float* __restrict__ out) {
    int i = blockIdx.x * blockDim.x + threadIdx.x;
    if (i < NN * FF) {
        g_acc1[i] = 0.f;
        g_acc2[i] = 0.f;
        g_acc3[i] = 0.f;
    }
    if (i < NN) g_cnt[i] = 0.f;
    if (i < 3 * NN) out[(size_t)5 * EE + i] = beta[i];
}
__global__ void k_headfold(const float* __restrict__ wl01, const float* __restrict__ bl01,
                           const float* __restrict__ wl02, const float* __restrict__ bl02,
                           const float* __restrict__ wl1, const float* __restrict__ bl1,
                           const float* __restrict__ wl2, const float* __restrict__ bl2) {
    int t = threadIdx.x;
    if (t < 128) {
        int k = t >> 2, j = t & 3;
        float s = 0.f;
#pragma unroll
        for (int m = 0; m < FF; m++) s += wl01[k * FF + m] * wl1[m * 4 + j];
        g_wx[k * 4 + j] = s;
    }
    if (t < 4) {
        float s = bl1[t];
#pragma unroll
        for (int m = 0; m < FF; m++) s += bl01[m] * wl1[m * 4 + t];
        g_bx[t] = s;
    }
    if (t >= 128 && t < 160) {
        int k = t - 128;
        float s = 0.f;
#pragma unroll
        for (int m = 0; m < FF; m++) s += wl02[k * FF + m] * wl2[m];
        g_wz[k] = s;
    }
    if (t == 160) {
        float s = bl2[0];
#pragma unroll
        for (int m = 0; m < FF; m++) s += bl02[m] * wl2[m];
        g_bz = s;
    }
}

// ---------------- node projection: 4-way column split, fused finalize ----------------
// 512 threads / 128 nodes. group g = tid>>7: g0 U[0:16], g1 U[16:32], g2 V[0:16], g3 V[16:32]
template <int KP>
__global__ __launch_bounds__(512) void k_node(const float* __restrict__ acca,
                                              const float* __restrict__ accb,
                                              const float* __restrict__ W0,
                                              const float* __restrict__ b0) {
    __shared__ __align__(16) float s_w[2 * KP * FF];
    __shared__ __align__(16) float s_b[FF];
    int tid = threadIdx.x;
    cpsh(s_w, W0, 2 * KP * FF, tid, 512);
    cpsh(s_b, b0, FF, tid, 512);
    __syncthreads();

    int g = tid >> 7;
    int isV = g >> 1, hf = g & 1;
    int n = blockIdx.x * 128 + (tid & 127);
    if (n >= NN) return;

    float inv = 1.0f / fmaxf(g_cnt[n], 1.0f);
    const float* ws = s_w + isV * KP * FF + hf * 16;

    V16 acc;
    if (isV) {
#pragma unroll
        for (int j = 0; j < 16; j++) acc.f[j] = 0.f;
    } else {
#pragma unroll
        for (int j = 0; j < 16; j++) acc.f[j] = s_b[hf * 16 + j];
    }

    const float* xpa = acca + (size_t)n * FF;
#pragma unroll
    for (int k4 = 0; k4 < 8; k4++) {
        float4 xv = *(const float4*)(xpa + k4 * 4);
        float vx[4] = {fmaxf(xv.x, 0.f) * inv, fmaxf(xv.y, 0.f) * inv,
                       fmaxf(xv.z, 0.f) * inv, fmaxf(xv.w, 0.f) * inv};
#pragma unroll
        for (int kk = 0; kk < 4; kk++) {
            const float* wr = ws + (k4 * 4 + kk) * FF;
            ull v = pk2(vx[kk]);
#pragma unroll
            for (int j = 0; j < 4; j++) {
                ulonglong2 w = *(const ulonglong2*)(wr + j * 4);
                ffma2(acc.u[2 * j + 0], v, w.x);
                ffma2(acc.u[2 * j + 1], v, w.y);
            }
        }
    }
    if (KP == 64) {
        const float* xpb = accb + (size_t)n * FF;
#pragma unroll
        for (int k4 = 0; k4 < 8; k4++) {
            float4 xv = *(const float4*)(xpb + k4 * 4);
            float vx[4] = {fmaxf(xv.x, 0.f) * inv, fmaxf(xv.y, 0.f) * inv,
                           fmaxf(xv.z, 0.f) * inv, fmaxf(xv.w, 0.f) * inv};
#pragma unroll
            for (int kk = 0; kk < 4; kk++) {
                const float* wr = ws + (32 + k4 * 4 + kk) * FF;
                ull v = pk2(vx[kk]);
#pragma unroll
                for (int j = 0; j < 4; j++) {
                    ulonglong2 w = *(const ulonglong2*)(wr + j * 4);
                    ffma2(acc.u[2 * j + 0], v, w.x);
                    ffma2(acc.u[2 * j + 1], v, w.y);
                }
            }
        }
    }

    float* up = g_uv + (size_t)n * 64 + isV * 32 + hf * 16;
#pragma unroll
    for (int j = 0; j < 16; j += 4) *(float4*)(up + j) = *(float4*)(acc.f + j);
}

// ---------------- conv1 (pair, split layer2) ----------------
__global__ __launch_bounds__(128, 4) void k_conv1(const float* __restrict__ ea,
                                                  const int* __restrict__ eidx,
                                                  const float* __restrict__ w10,
                                                  const float* __restrict__ b10,
                                                  const float* __restrict__ w11,
                                                  const float* __restrict__ b11) {
    __shared__ __align__(16) float s_w0[4 * FF];
    __shared__ __align__(16) float s_b0[FF];
    __shared__ __align__(16) float s_w1[FF * FF];
    __shared__ __align__(16) float s_b1[FF];
    int tid = threadIdx.x, nt = blockDim.x;
    cpsh(s_w0, w10, 4 * FF, tid, nt);
    cpsh(s_b0, b10, FF, tid, nt);
    cpsh(s_w1, w11, FF * FF, tid, nt);
    cpsh(s_b1, b11, FF, tid, nt);
    __syncthreads();

    int p = blockIdx.x * nt + tid;
    if (p >= HALF_E) return;
    int e0 = 2 * p, e1 = 2 * p + 1;

    float4 a0 = *(const float4*)(ea + (size_t)e0 * 4);
    float4 a1 = *(const float4*)(ea + (size_t)e1 * 4);
    V32 h0, h1;
    ldbias(h0, s_b0);
    ldbias(h1, s_b0);
    fmarow2p(h0, h1, pk2(a0.x), pk2(a1.x), s_w0);
    fmarow2p(h0, h1, pk2(a0.y), pk2(a1.y), s_w0 + FF);
    fmarow2p(h0, h1, pk2(a0.z), pk2(a1.z), s_w0 + 2 * FF);
    fmarow2p(h0, h1, pk2(a0.w), pk2(a1.w), s_w0 + 3 * FF);
    relu32(h0);
    relu32(h1);

    int r0 = eidx[e0], r1 = eidx[e1];
#pragma unroll
    for (int hf = 0; hf < 2; hf++) {
        V16 o0, o1;
        layer2ph(o0, o1, h0, h1, s_w1, s_b1, hf);
        scatter16(g_acc1 + (size_t)r0 * FF + hf * 16, o0);
        scatter16(g_acc1 + (size_t)r1 * FF + hf * 16, o1);
        store_relu16(g_e1 + (size_t)e0 * FF + hf * 16, o0);
        store_relu16(g_e1 + (size_t)e1 * FF + hf * 16, o1);
    }
    atomicAdd(&g_cnt[r0], 1.0f);
    atomicAdd(&g_cnt[r1], 1.0f);
}

// ---------------- edge2 ----------------
__global__ __launch_bounds__(128, 4) void k_edge2(const float* __restrict__ ea,
                                                  const int* __restrict__ eidx,
                                                  const float* __restrict__ w20,
                                                  const float* __restrict__ w21,
                                                  const float* __restrict__ b21) {
    __shared__ __align__(16) float s_w0e[36 * FF];
    __shared__ __align__(16) float s_w1[FF * FF];
    __shared__ __align__(16) float s_b1[FF];
    int tid = threadIdx.x, nt = blockDim.x;
    cpsh(s_w0e, w20 + 64 * FF, 36 * FF, tid, nt);
    cpsh(s_w1, w21, FF * FF, tid, nt);
    cpsh(s_b1, b21, FF, tid, nt);
    __syncthreads();

    int p = blockIdx.x * nt + tid;
    if (p >= HALF_E) return;
    int e0 = 2 * p, e1 = 2 * p + 1;
    int r0 = eidx[e0], c0 = eidx[EE + e0];
    int r1 = eidx[e1], c1 = eidx[EE + e1];

    V32 h0, h1;
    uvinit(h0, r0, c0);
    uvinit(h1, r1, c1);

    float4 a0 = *(const float4*)(ea + (size_t)e0 * 4);
    float4 a1 = *(const float4*)(ea + (size_t)e1 * 4);
    fmarow2p(h0, h1, pk2(a0.x), pk2(a1.x), s_w0e);
    fmarow2p(h0, h1, pk2(a0.y), pk2(a1.y), s_w0e + FF);
    fmarow2p(h0, h1, pk2(a0.z), pk2(a1.z), s_w0e + 2 * FF);
    fmarow2p(h0, h1, pk2(a0.w), pk2(a1.w), s_w0e + 3 * FF);
    seg32p(h0, h1, g_e1 + (size_t)e0 * FF, g_e1 + (size_t)e1 * FF, s_w0e + 4 * FF);
    relu32(h0);
    relu32(h1);

#pragma unroll
    for (int hf = 0; hf < 2; hf++) {
        V16 o0, o1;
        layer2ph(o0, o1, h0, h1, s_w1, s_b1, hf);
        scatter16(g_acc2 + (size_t)r0 * FF + hf * 16, o0);
        scatter16(g_acc2 + (size_t)r1 * FF + hf * 16, o1);
        store_relu16(g_e2 + (size_t)e0 * FF + hf * 16, o0);
        store_relu16(g_e2 + (size_t)e1 * FF + hf * 16, o1);
    }
}

// ---------------- edge3 ----------------
__global__ __launch_bounds__(128, 4) void k_edge3(const int* __restrict__ eidx,
                                                  const float* __restrict__ w30,
                                                  const float* __restrict__ w31,
                                                  const float* __restrict__ b31) {
    __shared__ __align__(16) float s_w0e[64 * FF];
    __shared__ __align__(16) float s_w1[FF * FF];
    __shared__ __align__(16) float s_b1[FF];
    int tid = threadIdx.x, nt = blockDim.x;
    cpsh(s_w0e, w30 + 128 * FF, 64 * FF, tid, nt);
    cpsh(s_w1, w31, FF * FF, tid, nt);
    cpsh(s_b1, b31, FF, tid, nt);
    __syncthreads();

    int p = blockIdx.x * nt + tid;
    if (p >= HALF_E) return;
    int e0 = 2 * p, e1 = 2 * p + 1;
    int r0 = eidx[e0], c0 = eidx[EE + e0];
    int r1 = eidx[e1], c1 = eidx[EE + e1];

    V32 h0, h1;
    uvinit(h0, r0, c0);
    uvinit(h1, r1, c1);
    seg32p(h0, h1, g_e2 + (size_t)e0 * FF, g_e2 + (size_t)e1 * FF, s_w0e);
    seg32p(h0, h1, g_e1 + (size_t)e0 * FF, g_e1 + (size_t)e1 * FF, s_w0e + 32 * FF);
    relu32(h0);
    relu32(h1);

#pragma unroll
    for (int hf = 0; hf < 2; hf++) {
        V16 o0, o1;
        layer2ph(o0, o1, h0, h1, s_w1, s_b1, hf);
        scatter16(g_acc3 + (size_t)r0 * FF + hf * 16, o0);
        scatter16(g_acc3 + (size_t)r1 * FF + hf * 16, o1);
        store_relu16(g_e3 + (size_t)e0 * FF + hf * 16, o0);
        store_relu16(g_e3 + (size_t)e1 * FF + hf * 16, o1);
    }
}

// ---------------- edge4 + folded heads ----------------
__global__ __launch_bounds__(128) void k_edge4(const float* __restrict__ ea,
                                               const int* __restrict__ eidx,
                                               const float* __restrict__ w40,
                                               const float* __restrict__ w41,
                                               const float* __restrict__ b41,
                                               float* __restrict__ out) {
    __shared__ __align__(16) float s_w0e[64 * FF];
    __shared__ __align__(16) float s_w1[FF * FF];
    __shared__ __align__(16) float s_b1[FF];
    __shared__ __align__(16) float s_wx[FF * 4];
    __shared__ __align__(16) float s_wz[FF];
    __shared__ float s_bx[4];
    __shared__ float s_bz;
    int tid = threadIdx.x, nt = blockDim.x;
    cpsh(s_w0e, w40 + 128 * FF, 64 * FF, tid, nt);
    cpsh(s_w1, w41, FF * FF, tid, nt);
    cpsh(s_b1, b41, FF, tid, nt);
    cpsh(s_wx, g_wx, FF * 4, tid, nt);
    cpsh(s_wz, g_wz, FF, tid, nt);
    if (tid < 4) s_bx[tid] = g_bx[tid];
    if (tid == 0) s_bz = g_bz;
    __syncthreads();

    int p = blockIdx.x * nt + tid;
    if (p >= HALF_E) return;
    int e0 = 2 * p, e1 = 2 * p + 1;
    int r0 = eidx[e0], c0 = eidx[EE + e0];
    int r1 = eidx[e1], c1 = eidx[EE + e1];

    V32 h0, h1;
    uvinit(h0, r0, c0);
    uvinit(h1, r1, c1);
    seg32p(h0, h1, g_e3 + (size_t)e0 * FF, g_e3 + (size_t)e1 * FF, s_w0e);
    seg32p(h0, h1, g_e2 + (size_t)e0 * FF, g_e2 + (size_t)e1 * FF, s_w0e + 32 * FF);
    relu32(h0);
    relu32(h1);

    V32 e40, e41;
    layer2p(e40, e41, h0, h1, s_w1, s_b1);
    relu32(e40);
    relu32(e41);

    float4 a0 = *(const float4*)(ea + (size_t)e0 * 4);
    float4 a1 = *(const float4*)(ea + (size_t)e1 * 4);
    float x00 = s_bx[0] + a0.x, x01 = s_bx[1] + a0.y, x02 = s_bx[2] + a0.z,
          x03 = s_bx[3] + a0.w;
    float x10 = s_bx[0] + a1.x, x11 = s_bx[1] + a1.y, x12 = s_bx[2] + a1.z,
          x13 = s_bx[3] + a1.w;
    float z0 = s_bz, z1 = s_bz;
#pragma unroll
    for (int k = 0; k < FF; k++) {
        float4 w = *(const float4*)(s_wx + k * 4);
        float wzk = s_wz[k];
        float v0 = e40.f[k], v1 = e41.f[k];
        x00 += v0 * w.x;
        x01 += v0 * w.y;
        x02 += v0 * w.z;
        x03 += v0 * w.w;
        z0 += v0 * wzk;
        x10 += v1 * w.x;
        x11 += v1 * w.y;
        x12 += v1 * w.z;
        x13 += v1 * w.w;
        z1 += v1 * wzk;
    }
    {
        float nrm = sqrtf(x00 * x00 + x01 * x01 + x02 * x02 + x03 * x03);
        float inv = 1.0f / fmaxf(nrm, 1e-12f);
        *(float4*)(out + (size_t)EE + (size_t)e0 * 4) =
            make_float4(x00 * inv, x01 * inv, x02 * inv, x03 * inv);
    }
    {
        float nrm = sqrtf(x10 * x10 + x11 * x11 + x12 * x12 + x13 * x13);
        float inv = 1.0f / fmaxf(nrm, 1e-12f);
        *(float4*)(out + (size_t)EE + (size_t)e1 * 4) =
            make_float4(x10 * inv, x11 * inv, x12 * inv, x13 * inv);
    }
    out[e0] = 1.0f / (1.0f + expf(-z0));
    out[e1] = 1.0f / (1.0f + expf(-z1));
}

// ---------------- launch ----------------
extern "C" void kernel_launch(void* const* d_in, const int* in_sizes, int n_in,
                              void* d_out, int out_size) {
    const int* eidx = (const int*)d_in[1];
    const float* ea = (const float*)d_in[2];
    const float* beta = (const float*)d_in[3];
    const float* w10 = (const float*)d_in[4];
    const float* b10 = (const float*)d_in[5];
    const float* w11 = (const float*)d_in[6];
    const float* b11 = (const float*)d_in[7];
    const float* w20 = (const float*)d_in[8];
    const float* b20 = (const float*)d_in[9];
    const float* w21 = (const float*)d_in[10];
    const float* b21 = (const float*)d_in[11];
    const float* w30 = (const float*)d_in[12];
    const float* b30 = (const float*)d_in[13];
    const float* w31 = (const float*)d_in[14];
    const float* b31 = (const float*)d_in[15];
    const float* w40 = (const float*)d_in[16];
    const float* b40 = (const float*)d_in[17];
    const float* w41 = (const float*)d_in[18];
    const float* b41 = (const float*)d_in[19];
    const float* wl01 = (const float*)d_in[20];
    const float* bl01 = (const float*)d_in[21];
    const float* wl02 = (const float*)d_in[22];
    const float* bl02 = (const float*)d_in[23];
    const float* wl1 = (const float*)d_in[24];
    const float* bl1 = (const float*)d_in[25];
    const float* wl2 = (const float*)d_in[26];
    const float* bl2 = (const float*)d_in[27];
    float* out = (float*)d_out;

    float *acc1p, *acc2p, *acc3p;
    cudaGetSymbolAddress((void**)&acc1p, g_acc1);
    cudaGetSymbolAddress((void**)&acc2p, g_acc2);
    cudaGetSymbolAddress((void**)&acc3p, g_acc3);

    const int T = 256;
    const int gridNF = (NN * FF + T - 1) / T;
    const int TB = 128;
    const int gridP = (HALF_E + TB - 1) / TB;
    const int gridN = (NN + 127) / 128;

    k_init<<<gridNF, T>>>(beta, out);
    k_headfold<<<1, 192>>>(wl01, bl01, wl02, bl02, wl1, bl1, wl2, bl2);
    k_conv1<<<gridP, TB>>>(ea, eidx, w10, b10, w11, b11);

    k_node<32><<<gridN, 512>>>(acc1p, nullptr, w20, b20);
    k_edge2<<<gridP, TB>>>(ea, eidx, w20, w21, b21);

    k_node<64><<<gridN, 512>>>(acc2p, acc1p, w30, b30);
    k_edge3<<<gridP, TB>>>(eidx, w30, w31, b31);

    k_node<64><<<gridN, 512>>>(acc3p, acc2p, w40, b40);
    k_edge4<<<gridP, TB>>>(ea, eidx, w40, w41, b41, out);
}

// round 10
// speedup vs baseline: 1.0931x; 1.0931x over previous
#include <cuda_runtime.h>
#include <math.h>

#define NN 50000
#define EE 400000
#define FF 32
#define HALF_E (EE / 2)

typedef unsigned long long ull;

// ---------------- scratch ----------------
__device__ __align__(128) float g_e1[(size_t)EE * FF];
__device__ __align__(128) float g_e2[(size_t)EE * FF];
__device__ __align__(128) float g_e3[(size_t)EE * FF];
__device__ __align__(128) float g_acc1[(size_t)NN * FF];
__device__ __align__(128) float g_acc2[(size_t)NN * FF];
__device__ __align__(128) float g_acc3[(size_t)NN * FF];
__device__ __align__(128) float g_uv[(size_t)NN * 64];
__device__ __align__(128) float g_cnt[NN];
__device__ __align__(16) float g_wx[FF * 4];
__device__ __align__(16) float g_bx[4];
__device__ __align__(16) float g_wz[FF];
__device__ float g_bz;

// ---------------- f32x2 helpers ----------------
__device__ __forceinline__ void ffma2(ull& d, ull a, ull b) {
    asm("fma.rn.f32x2 %0, %1, %2, %0;" : "+l"(d) : "l"(a), "l"(b));
}
__device__ __forceinline__ ull pk2(float v) {
    ull r;
    asm("mov.b64 %0, {%1, %1};" : "=l"(r) : "f"(v));
    return r;
}
union V32 {
    float f[FF];
    ull u[FF / 2];
};

__device__ __forceinline__ void cpsh(float* dst, const float* src, int n, int tid, int nt) {
    for (int i = tid; i < n; i += nt) dst[i] = src[i];
}
__device__ __forceinline__ void ldbias(V32& h, const float* __restrict__ b) {
#pragma unroll
    for (int j = 0; j < FF; j++) h.f[j] = b[j];
}
__device__ __forceinline__ void relu32(V32& h) {
#pragma unroll
    for (int j = 0; j < FF; j++) h.f[j] = fmaxf(h.f[j], 0.f);
}
__device__ __forceinline__ void red4(float* __restrict__ a, float x, float y, float z, float w) {
    asm volatile("red.global.add.v4.f32 [%0], {%1, %2, %3, %4};" ::"l"(a), "f"(x), "f"(y),
                 "f"(z), "f"(w)
                 : "memory");
}
__device__ __forceinline__ void scatter32(float* __restrict__ acc, const V32& o) {
#pragma unroll
    for (int j = 0; j < FF; j += 4) red4(acc + j, o.f[j], o.f[j + 1], o.f[j + 2], o.f[j + 3]);
}
__device__ __forceinline__ void store_relu32(float* __restrict__ dst, const V32& o) {
#pragma unroll
    for (int j = 0; j < FF; j += 4) {
        *(float4*)(dst + j) = make_float4(fmaxf(o.f[j], 0.f), fmaxf(o.f[j + 1], 0.f),
                                          fmaxf(o.f[j + 2], 0.f), fmaxf(o.f[j + 3], 0.f));
    }
}

__device__ __forceinline__ void fmarow1(V32& h, ull v, const float* __restrict__ wr) {
#pragma unroll
    for (int j = 0; j < 8; j++) {
        ulonglong2 w = *(const ulonglong2*)(wr + j * 4);
        ffma2(h.u[2 * j + 0], v, w.x);
        ffma2(h.u[2 * j + 1], v, w.y);
    }
}
__device__ __forceinline__ void fmarow2p(V32& h0, V32& h1, ull v0, ull v1,
                                         const float* __restrict__ wr) {
#pragma unroll
    for (int j = 0; j < 8; j++) {
        ulonglong2 w = *(const ulonglong2*)(wr + j * 4);
        ffma2(h0.u[2 * j + 0], v0, w.x);
        ffma2(h0.u[2 * j + 1], v0, w.y);
        ffma2(h1.u[2 * j + 0], v1, w.x);
        ffma2(h1.u[2 * j + 1], v1, w.y);
    }
}
__device__ __forceinline__ void seg32p(V32& h0, V32& h1, const float* __restrict__ s0,
                                       const float* __restrict__ s1,
                                       const float* __restrict__ ws) {
#pragma unroll
    for (int k = 0; k < FF; k += 4) {
        float4 a = *(const float4*)(s0 + k);
        float4 b = *(const float4*)(s1 + k);
        fmarow2p(h0, h1, pk2(a.x), pk2(b.x), ws + (k + 0) * FF);
        fmarow2p(h0, h1, pk2(a.y), pk2(b.y), ws + (k + 1) * FF);
        fmarow2p(h0, h1, pk2(a.z), pk2(b.z), ws + (k + 2) * FF);
        fmarow2p(h0, h1, pk2(a.w), pk2(b.w), ws + (k + 3) * FF);
    }
}
__device__ __forceinline__ void layer2p(V32& o0, V32& o1, const V32& h0, const V32& h1,
                                        const float* __restrict__ sw1,
                                        const float* __restrict__ sb1) {
    ldbias(o0, sb1);
    ldbias(o1, sb1);
#pragma unroll
    for (int k = 0; k < FF; k++) fmarow2p(o0, o1, pk2(h0.f[k]), pk2(h1.f[k]), sw1 + k * FF);
}
__device__ __forceinline__ void uvinit(V32& h, int r, int c) {
    const float* U = g_uv + (size_t)r * 64;
    const float* V = g_uv + (size_t)c * 64 + 32;
#pragma unroll
    for (int j = 0; j < FF; j += 4) {
        float4 a = *(const float4*)(U + j);
        float4 b = *(const float4*)(V + j);
        h.f[j + 0] = a.x + b.x;
        h.f[j + 1] = a.y + b.y;
        h.f[j + 2] = a.z + b.z;
        h.f[j + 3] = a.w + b.w;
    }
}

// ---------------- init / head fold ----------------
__global__ void k_init(const float* __restrict__ beta, float* __restrict__ out) {
    int i = blockIdx.x * blockDim.x + threadIdx.x;
    if (i < NN * FF) {
        g_acc1[i] = 0.f;
        g_acc2[i] = 0.f;
        g_acc3[i] = 0.f;
    }
    if (i < NN) g_cnt[i] = 0.f;
    if (i < 3 * NN) out[(size_t)5 * EE + i] = beta[i];
}
__global__ void k_headfold(const float* __restrict__ wl01, const float* __restrict__ bl01,
                           const float* __restrict__ wl02, const float* __restrict__ bl02,
                           const float* __restrict__ wl1, const float* __restrict__ bl1,
                           const float* __restrict__ wl2, const float* __restrict__ bl2) {
    int t = threadIdx.x;
    if (t < 128) {
        int k = t >> 2, j = t & 3;
        float s = 0.f;
#pragma unroll
        for (int m = 0; m < FF; m++) s += wl01[k * FF + m] * wl1[m * 4 + j];
        g_wx[k * 4 + j] = s;
    }
    if (t < 4) {
        float s = bl1[t];
#pragma unroll
        for (int m = 0; m < FF; m++) s += bl01[m] * wl1[m * 4 + t];
        g_bx[t] = s;
    }
    if (t >= 128 && t < 160) {
        int k = t - 128;
        float s = 0.f;
#pragma unroll
        for (int m = 0; m < FF; m++) s += wl02[k * FF + m] * wl2[m];
        g_wz[k] = s;
    }
    if (t == 160) {
        float s = bl2[0];
#pragma unroll
        for (int m = 0; m < FF; m++) s += bl02[m] * wl2[m];
        g_bz = s;
    }
}

// ---------------- node projection (R8 form: 2-way U/V split, fused finalize) ----------------
template <int KP>
__global__ __launch_bounds__(256) void k_node(const float* __restrict__ acca,
                                              const float* __restrict__ accb,
                                              const float* __restrict__ W0,
                                              const float* __restrict__ b0) {
    __shared__ __align__(16) float s_w[2 * KP * FF];
    __shared__ __align__(16) float s_b[FF];
    int tid = threadIdx.x;

    // prefetch count before staging barrier
    int n = blockIdx.x * 128 + (tid & 127);
    float cnt = (n < NN) ? g_cnt[n] : 1.0f;

    cpsh(s_w, W0, 2 * KP * FF, tid, 256);
    cpsh(s_b, b0, FF, tid, 256);
    __syncthreads();

    int isV = tid >> 7;
    if (n >= NN) return;

    float inv = 1.0f / fmaxf(cnt, 1.0f);
    const float* ws = s_w + (isV ? KP * FF : 0);

    V32 acc;
    if (isV) {
#pragma unroll
        for (int j = 0; j < FF; j++) acc.f[j] = 0.f;
    } else {
        ldbias(acc, s_b);
    }

    const float* xpa = acca + (size_t)n * FF;
#pragma unroll
    for (int k4 = 0; k4 < 8; k4++) {
        float4 xv = *(const float4*)(xpa + k4 * 4);
        xv.x = fmaxf(xv.x, 0.f) * inv;
        xv.y = fmaxf(xv.y, 0.f) * inv;
        xv.z = fmaxf(xv.z, 0.f) * inv;
        xv.w = fmaxf(xv.w, 0.f) * inv;
        int k = k4 * 4;
        fmarow1(acc, pk2(xv.x), ws + (k + 0) * FF);
        fmarow1(acc, pk2(xv.y), ws + (k + 1) * FF);
        fmarow1(acc, pk2(xv.z), ws + (k + 2) * FF);
        fmarow1(acc, pk2(xv.w), ws + (k + 3) * FF);
    }
    if (KP == 64) {
        const float* xpb = accb + (size_t)n * FF;
#pragma unroll
        for (int k4 = 0; k4 < 8; k4++) {
            float4 xv = *(const float4*)(xpb + k4 * 4);
            xv.x = fmaxf(xv.x, 0.f) * inv;
            xv.y = fmaxf(xv.y, 0.f) * inv;
            xv.z = fmaxf(xv.z, 0.f) * inv;
            xv.w = fmaxf(xv.w, 0.f) * inv;
            int k = 32 + k4 * 4;
            fmarow1(acc, pk2(xv.x), ws + (k + 0) * FF);
            fmarow1(acc, pk2(xv.y), ws + (k + 1) * FF);
            fmarow1(acc, pk2(xv.z), ws + (k + 2) * FF);
            fmarow1(acc, pk2(xv.w), ws + (k + 3) * FF);
        }
    }

    float* up = g_uv + (size_t)n * 64 + isV * 32;
#pragma unroll
    for (int j = 0; j < FF; j += 4) *(float4*)(up + j) = *(float4*)(acc.f + j);
}

// ---------------- conv1 (pair; prefetch before barrier) ----------------
__global__ __launch_bounds__(128) void k_conv1(const float* __restrict__ ea,
                                               const int* __restrict__ eidx,
                                               const float* __restrict__ w10,
                                               const float* __restrict__ b10,
                                               const float* __restrict__ w11,
                                               const float* __restrict__ b11) {
    __shared__ __align__(16) float s_w0[4 * FF];
    __shared__ __align__(16) float s_b0[FF];
    __shared__ __align__(16) float s_w1[FF * FF];
    __shared__ __align__(16) float s_b1[FF];
    int tid = threadIdx.x, nt = blockDim.x;

    int p = blockIdx.x * nt + tid;
    bool act = p < HALF_E;
    int e0 = 2 * p, e1 = 2 * p + 1;
    float4 a0, a1;
    int r0 = 0, r1 = 0;
    if (act) {
        a0 = *(const float4*)(ea + (size_t)e0 * 4);
        a1 = *(const float4*)(ea + (size_t)e1 * 4);
        r0 = eidx[e0];
        r1 = eidx[e1];
    }

    cpsh(s_w0, w10, 4 * FF, tid, nt);
    cpsh(s_b0, b10, FF, tid, nt);
    cpsh(s_w1, w11, FF * FF, tid, nt);
    cpsh(s_b1, b11, FF, tid, nt);
    __syncthreads();
    if (!act) return;

    V32 h0, h1;
    ldbias(h0, s_b0);
    ldbias(h1, s_b0);
    fmarow2p(h0, h1, pk2(a0.x), pk2(a1.x), s_w0);
    fmarow2p(h0, h1, pk2(a0.y), pk2(a1.y), s_w0 + FF);
    fmarow2p(h0, h1, pk2(a0.z), pk2(a1.z), s_w0 + 2 * FF);
    fmarow2p(h0, h1, pk2(a0.w), pk2(a1.w), s_w0 + 3 * FF);
    relu32(h0);
    relu32(h1);

    V32 o0, o1;
    layer2p(o0, o1, h0, h1, s_w1, s_b1);

    scatter32(g_acc1 + (size_t)r0 * FF, o0);
    scatter32(g_acc1 + (size_t)r1 * FF, o1);
    atomicAdd(&g_cnt[r0], 1.0f);
    atomicAdd(&g_cnt[r1], 1.0f);
    store_relu32(g_e1 + (size_t)e0 * FF, o0);
    store_relu32(g_e1 + (size_t)e1 * FF, o1);
}

// ---------------- edge2 (prefetch idx+UV+ea before barrier) ----------------
__global__ __launch_bounds__(128) void k_edge2(const float* __restrict__ ea,
                                               const int* __restrict__ eidx,
                                               const float* __restrict__ w20,
                                               const float* __restrict__ w21,
                                               const float* __restrict__ b21) {
    __shared__ __align__(16) float s_w0e[36 * FF];
    __shared__ __align__(16) float s_w1[FF * FF];
    __shared__ __align__(16) float s_b1[FF];
    int tid = threadIdx.x, nt = blockDim.x;

    int p = blockIdx.x * nt + tid;
    bool act = p < HALF_E;
    int e0 = 2 * p, e1 = 2 * p + 1;
    int r0 = 0, c0 = 0, r1 = 0, c1 = 0;
    float4 a0, a1;
    V32 h0, h1;
    if (act) {
        r0 = eidx[e0];
        c0 = eidx[EE + e0];
        r1 = eidx[e1];
        c1 = eidx[EE + e1];
        uvinit(h0, r0, c0);
        uvinit(h1, r1, c1);
        a0 = *(const float4*)(ea + (size_t)e0 * 4);
        a1 = *(const float4*)(ea + (size_t)e1 * 4);
    }

    cpsh(s_w0e, w20 + 64 * FF, 36 * FF, tid, nt);
    cpsh(s_w1, w21, FF * FF, tid, nt);
    cpsh(s_b1, b21, FF, tid, nt);
    __syncthreads();
    if (!act) return;

    fmarow2p(h0, h1, pk2(a0.x), pk2(a1.x), s_w0e);
    fmarow2p(h0, h1, pk2(a0.y), pk2(a1.y), s_w0e + FF);
    fmarow2p(h0, h1, pk2(a0.z), pk2(a1.z), s_w0e + 2 * FF);
    fmarow2p(h0, h1, pk2(a0.w), pk2(a1.w), s_w0e + 3 * FF);
    seg32p(h0, h1, g_e1 + (size_t)e0 * FF, g_e1 + (size_t)e1 * FF, s_w0e + 4 * FF);
    relu32(h0);
    relu32(h1);

    V32 o0, o1;
    layer2p(o0, o1, h0, h1, s_w1, s_b1);

    scatter32(g_acc2 + (size_t)r0 * FF, o0);
    scatter32(g_acc2 + (size_t)r1 * FF, o1);
    store_relu32(g_e2 + (size_t)e0 * FF, o0);
    store_relu32(g_e2 + (size_t)e1 * FF, o1);
}

// ---------------- edge3 ----------------
__global__ __launch_bounds__(128) void k_edge3(const int* __restrict__ eidx,
                                               const float* __restrict__ w30,
                                               const float* __restrict__ w31,
                                               const float* __restrict__ b31) {
    __shared__ __align__(16) float s_w0e[64 * FF];
    __shared__ __align__(16) float s_w1[FF * FF];
    __shared__ __align__(16) float s_b1[FF];
    int tid = threadIdx.x, nt = blockDim.x;

    int p = blockIdx.x * nt + tid;
    bool act = p < HALF_E;
    int e0 = 2 * p, e1 = 2 * p + 1;
    int r0 = 0, c0 = 0, r1 = 0, c1 = 0;
    V32 h0, h1;
    if (act) {
        r0 = eidx[e0];
        c0 = eidx[EE + e0];
        r1 = eidx[e1];
        c1 = eidx[EE + e1];
        uvinit(h0, r0, c0);
        uvinit(h1, r1, c1);
    }

    cpsh(s_w0e, w30 + 128 * FF, 64 * FF, tid, nt);
    cpsh(s_w1, w31, FF * FF, tid, nt);
    cpsh(s_b1, b31, FF, tid, nt);
    __syncthreads();
    if (!act) return;

    seg32p(h0, h1, g_e2 + (size_t)e0 * FF, g_e2 + (size_t)e1 * FF, s_w0e);
    seg32p(h0, h1, g_e1 + (size_t)e0 * FF, g_e1 + (size_t)e1 * FF, s_w0e + 32 * FF);
    relu32(h0);
    relu32(h1);

    V32 o0, o1;
    layer2p(o0, o1, h0, h1, s_w1, s_b1);

    scatter32(g_acc3 + (size_t)r0 * FF, o0);
    scatter32(g_acc3 + (size_t)r1 * FF, o1);
    store_relu32(g_e3 + (size_t)e0 * FF, o0);
    store_relu32(g_e3 + (size_t)e1 * FF, o1);
}

// ---------------- edge4 + folded heads ----------------
__global__ __launch_bounds__(128) void k_edge4(const float* __restrict__ ea,
                                               const int* __restrict__ eidx,
                                               const float* __restrict__ w40,
                                               const float* __restrict__ w41,
                                               const float* __restrict__ b41,
                                               float* __restrict__ out) {
    __shared__ __align__(16) float s_w0e[64 * FF];
    __shared__ __align__(16) float s_w1[FF * FF];
    __shared__ __align__(16) float s_b1[FF];
    __shared__ __align__(16) float s_wx[FF * 4];
    __shared__ __align__(16) float s_wz[FF];
    __shared__ float s_bx[4];
    __shared__ float s_bz;
    int tid = threadIdx.x, nt = blockDim.x;

    int p = blockIdx.x * nt + tid;
    bool act = p < HALF_E;
    int e0 = 2 * p, e1 = 2 * p + 1;
    int r0 = 0, c0 = 0, r1 = 0, c1 = 0;
    float4 a0, a1;
    V32 h0, h1;
    if (act) {
        r0 = eidx[e0];
        c0 = eidx[EE + e0];
        r1 = eidx[e1];
        c1 = eidx[EE + e1];
        uvinit(h0, r0, c0);
        uvinit(h1, r1, c1);
        a0 = *(const float4*)(ea + (size_t)e0 * 4);
        a1 = *(const float4*)(ea + (size_t)e1 * 4);
    }

    cpsh(s_w0e, w40 + 128 * FF, 64 * FF, tid, nt);
    cpsh(s_w1, w41, FF * FF, tid, nt);
    cpsh(s_b1, b41, FF, tid, nt);
    cpsh(s_wx, g_wx, FF * 4, tid, nt);
    cpsh(s_wz, g_wz, FF, tid, nt);
    if (tid < 4) s_bx[tid] = g_bx[tid];
    if (tid == 0) s_bz = g_bz;
    __syncthreads();
    if (!act) return;

    seg32p(h0, h1, g_e3 + (size_t)e0 * FF, g_e3 + (size_t)e1 * FF, s_w0e);
    seg32p(h0, h1, g_e2 + (size_t)e0 * FF, g_e2 + (size_t)e1 * FF, s_w0e + 32 * FF);
    relu32(h0);
    relu32(h1);

    V32 e40, e41;
    layer2p(e40, e41, h0, h1, s_w1, s_b1);
    relu32(e40);
    relu32(e41);

    float x00 = s_bx[0] + a0.x, x01 = s_bx[1] + a0.y, x02 = s_bx[2] + a0.z,
          x03 = s_bx[3] + a0.w;
    float x10 = s_bx[0] + a1.x, x11 = s_bx[1] + a1.y, x12 = s_bx[2] + a1.z,
          x13 = s_bx[3] + a1.w;
    float z0 = s_bz, z1 = s_bz;
#pragma unroll
    for (int k = 0; k < FF; k++) {
        float4 w = *(const float4*)(s_wx + k * 4);
        float wzk = s_wz[k];
        float v0 = e40.f[k], v1 = e41.f[k];
        x00 += v0 * w.x;
        x01 += v0 * w.y;
        x02 += v0 * w.z;
        x03 += v0 * w.w;
        z0 += v0 * wzk;
        x10 += v1 * w.x;
        x11 += v1 * w.y;
        x12 += v1 * w.z;
        x13 += v1 * w.w;
        z1 += v1 * wzk;
    }
    {
        float nrm = sqrtf(x00 * x00 + x01 * x01 + x02 * x02 + x03 * x03);
        float inv = 1.0f / fmaxf(nrm, 1e-12f);
        *(float4*)(out + (size_t)EE + (size_t)e0 * 4) =
            make_float4(x00 * inv, x01 * inv, x02 * inv, x03 * inv);
    }
    {
        float nrm = sqrtf(x10 * x10 + x11 * x11 + x12 * x12 + x13 * x13);
        float inv = 1.0f / fmaxf(nrm, 1e-12f);
        *(float4*)(out + (size_t)EE + (size_t)e1 * 4) =
            make_float4(x10 * inv, x11 * inv, x12 * inv, x13 * inv);
    }
    out[e0] = 1.0f / (1.0f + expf(-z0));
    out[e1] = 1.0f / (1.0f + expf(-z1));
}

// ---------------- launch ----------------
extern "C" void kernel_launch(void* const* d_in, const int* in_sizes, int n_in,
                              void* d_out, int out_size) {
    const int* eidx = (const int*)d_in[1];
    const float* ea = (const float*)d_in[2];
    const float* beta = (const float*)d_in[3];
    const float* w10 = (const float*)d_in[4];
    const float* b10 = (const float*)d_in[5];
    const float* w11 = (const float*)d_in[6];
    const float* b11 = (const float*)d_in[7];
    const float* w20 = (const float*)d_in[8];
    const float* b20 = (const float*)d_in[9];
    const float* w21 = (const float*)d_in[10];
    const float* b21 = (const float*)d_in[11];
    const float* w30 = (const float*)d_in[12];
    const float* b30 = (const float*)d_in[13];
    const float* w31 = (const float*)d_in[14];
    const float* b31 = (const float*)d_in[15];
    const float* w40 = (const float*)d_in[16];
    const float* b40 = (const float*)d_in[17];
    const float* w41 = (const float*)d_in[18];
    const float* b41 = (const float*)d_in[19];
    const float* wl01 = (const float*)d_in[20];
    const float* bl01 = (const float*)d_in[21];
    const float* wl02 = (const float*)d_in[22];
    const float* bl02 = (const float*)d_in[23];
    const float* wl1 = (const float*)d_in[24];
    const float* bl1 = (const float*)d_in[25];
    const float* wl2 = (const float*)d_in[26];
    const float* bl2 = (const float*)d_in[27];
    float* out = (float*)d_out;

    float *acc1p, *acc2p, *acc3p;
    cudaGetSymbolAddress((void**)&acc1p, g_acc1);
    cudaGetSymbolAddress((void**)&acc2p, g_acc2);
    cudaGetSymbolAddress((void**)&acc3p, g_acc3);

    const int T = 256;
    const int gridNF = (NN * FF + T - 1) / T;
    const int TB = 128;
    const int gridP = (HALF_E + TB - 1) / TB;
    const int gridN = (NN + 127) / 128;

    k_init<<<gridNF, T>>>(beta, out);
    k_headfold<<<1, 192>>>(wl01, bl01, wl02, bl02, wl1, bl1, wl2, bl2);
    k_conv1<<<gridP, TB>>>(ea, eidx, w10, b10, w11, b11);

    k_node<32><<<gridN, 256>>>(acc1p, nullptr, w20, b20);
    k_edge2<<<gridP, TB>>>(ea, eidx, w20, w21, b21);

    k_node<64><<<gridN, 256>>>(acc2p, acc1p, w30, b30);
    k_edge3<<<gridP, TB>>>(eidx, w30, w31, b31);

    k_node<64><<<gridN, 256>>>(acc3p, acc2p, w40, b40);
    k_edge4<<<gridP, TB>>>(ea, eidx, w40, w41, b41, out);
}

// round 11
// speedup vs baseline: 1.0984x; 1.0048x over previous
#include <cuda_runtime.h>
#include <math.h>

#define NN 50000
#define EE 400000
#define FF 32
#define HALF_E (EE / 2)

typedef unsigned long long ull;

// ---------------- scratch ----------------
// e-feature buffers are TRANSPOSED: [FF][EE] (k-major), element (k, e) at k*EE + e
__device__ __align__(128) float g_e1[(size_t)EE * FF];
__device__ __align__(128) float g_e2[(size_t)EE * FF];
__device__ __align__(128) float g_e3[(size_t)EE * FF];
__device__ __align__(128) float g_acc1[(size_t)NN * FF];
__device__ __align__(128) float g_acc2[(size_t)NN * FF];
__device__ __align__(128) float g_acc3[(size_t)NN * FF];
__device__ __align__(128) float g_uv[(size_t)NN * 64];
__device__ __align__(128) float g_cnt[NN];
__device__ __align__(16) float g_wx[FF * 4];
__device__ __align__(16) float g_bx[4];
__device__ __align__(16) float g_wz[FF];
__device__ float g_bz;

// ---------------- f32x2 helpers ----------------
__device__ __forceinline__ void ffma2(ull& d, ull a, ull b) {
    asm("fma.rn.f32x2 %0, %1, %2, %0;" : "+l"(d) : "l"(a), "l"(b));
}
__device__ __forceinline__ ull pk2(float v) {
    ull r;
    asm("mov.b64 %0, {%1, %1};" : "=l"(r) : "f"(v));
    return r;
}
union V32 {
    float f[FF];
    ull u[FF / 2];
};

__device__ __forceinline__ void cpsh(float* dst, const float* src, int n, int tid, int nt) {
    for (int i = tid; i < n; i += nt) dst[i] = src[i];
}
__device__ __forceinline__ void ldbias(V32& h, const float* __restrict__ b) {
#pragma unroll
    for (int j = 0; j < FF; j++) h.f[j] = b[j];
}
__device__ __forceinline__ void relu32(V32& h) {
#pragma unroll
    for (int j = 0; j < FF; j++) h.f[j] = fmaxf(h.f[j], 0.f);
}
__device__ __forceinline__ void red4(float* __restrict__ a, float x, float y, float z, float w) {
    asm volatile("red.global.add.v4.f32 [%0], {%1, %2, %3, %4};" ::"l"(a), "f"(x), "f"(y),
                 "f"(z), "f"(w)
                 : "memory");
}
__device__ __forceinline__ void scatter32(float* __restrict__ acc, const V32& o) {
#pragma unroll
    for (int j = 0; j < FF; j += 4) red4(acc + j, o.f[j], o.f[j + 1], o.f[j + 2], o.f[j + 3]);
}

__device__ __forceinline__ void fmarow1(V32& h, ull v, const float* __restrict__ wr) {
#pragma unroll
    for (int j = 0; j < 8; j++) {
        ulonglong2 w = *(const ulonglong2*)(wr + j * 4);
        ffma2(h.u[2 * j + 0], v, w.x);
        ffma2(h.u[2 * j + 1], v, w.y);
    }
}
__device__ __forceinline__ void fmarow2p(V32& h0, V32& h1, ull v0, ull v1,
                                         const float* __restrict__ wr) {
#pragma unroll
    for (int j = 0; j < 8; j++) {
        ulonglong2 w = *(const ulonglong2*)(wr + j * 4);
        ffma2(h0.u[2 * j + 0], v0, w.x);
        ffma2(h0.u[2 * j + 1], v0, w.y);
        ffma2(h1.u[2 * j + 0], v1, w.x);
        ffma2(h1.u[2 * j + 1], v1, w.y);
    }
}
// transposed-feature segment: gT is [32][EE]; loads (v_e0, v_e1) as float2 per k
__device__ __forceinline__ void seg32pT(V32& h0, V32& h1, const float* __restrict__ gT,
                                        int e0, const float* __restrict__ ws) {
    const float* p = gT + e0;
#pragma unroll
    for (int k = 0; k < FF; k++) {
        float2 v = *(const float2*)(p + (size_t)k * EE);
        fmarow2p(h0, h1, pk2(v.x), pk2(v.y), ws + k * FF);
    }
}
__device__ __forceinline__ void layer2p(V32& o0, V32& o1, const V32& h0, const V32& h1,
                                        const float* __restrict__ sw1,
                                        const float* __restrict__ sb1) {
    ldbias(o0, sb1);
    ldbias(o1, sb1);
#pragma unroll
    for (int k = 0; k < FF; k++) fmarow2p(o0, o1, pk2(h0.f[k]), pk2(h1.f[k]), sw1 + k * FF);
}
// transposed store: (relu(o0[j]), relu(o1[j])) -> gT[j][e0..e0+1]
__device__ __forceinline__ void store_relu2T(float* __restrict__ gT, int e0, const V32& o0,
                                             const V32& o1) {
    float* p = gT + e0;
#pragma unroll
    for (int j = 0; j < FF; j++) {
        float2 t = make_float2(fmaxf(o0.f[j], 0.f), fmaxf(o1.f[j], 0.f));
        *(float2*)(p + (size_t)j * EE) = t;
    }
}
__device__ __forceinline__ void uvinit(V32& h, int r, int c) {
    const float* U = g_uv + (size_t)r * 64;
    const float* V = g_uv + (size_t)c * 64 + 32;
#pragma unroll
    for (int j = 0; j < FF; j += 4) {
        float4 a = *(const float4*)(U + j);
        float4 b = *(const float4*)(V + j);
        h.f[j + 0] = a.x + b.x;
        h.f[j + 1] = a.y + b.y;
        h.f[j + 2] = a.z + b.z;
        h.f[j + 3] = a.w + b.w;
    }
}

// ---------------- init / head fold ----------------
__global__ void k_init(const float* __restrict__ beta, float* __restrict__ out) {
    int i = blockIdx.x * blockDim.x + threadIdx.x;
    if (i < NN * FF) {
        g_acc1[i] = 0.f;
        g_acc2[i] = 0.f;
        g_acc3[i] = 0.f;
    }
    if (i < NN) g_cnt[i] = 0.f;
    if (i < 3 * NN) out[(size_t)5 * EE + i] = beta[i];
}
__global__ void k_headfold(const float* __restrict__ wl01, const float* __restrict__ bl01,
                           const float* __restrict__ wl02, const float* __restrict__ bl02,
                           const float* __restrict__ wl1, const float* __restrict__ bl1,
                           const float* __restrict__ wl2, const float* __restrict__ bl2) {
    int t = threadIdx.x;
    if (t < 128) {
        int k = t >> 2, j = t & 3;
        float s = 0.f;
#pragma unroll
        for (int m = 0; m < FF; m++) s += wl01[k * FF + m] * wl1[m * 4 + j];
        g_wx[k * 4 + j] = s;
    }
    if (t < 4) {
        float s = bl1[t];
#pragma unroll
        for (int m = 0; m < FF; m++) s += bl01[m] * wl1[m * 4 + t];
        g_bx[t] = s;
    }
    if (t >= 128 && t < 160) {
        int k = t - 128;
        float s = 0.f;
#pragma unroll
        for (int m = 0; m < FF; m++) s += wl02[k * FF + m] * wl2[m];
        g_wz[k] = s;
    }
    if (t == 160) {
        float s = bl2[0];
#pragma unroll
        for (int m = 0; m < FF; m++) s += bl02[m] * wl2[m];
        g_bz = s;
    }
}

// ---------------- node projection (2-way U/V split, fused finalize) ----------------
template <int KP>
__global__ __launch_bounds__(256) void k_node(const float* __restrict__ acca,
                                              const float* __restrict__ accb,
                                              const float* __restrict__ W0,
                                              const float* __restrict__ b0) {
    __shared__ __align__(16) float s_w[2 * KP * FF];
    __shared__ __align__(16) float s_b[FF];
    int tid = threadIdx.x;

    int n = blockIdx.x * 128 + (tid & 127);
    float cnt = (n < NN) ? g_cnt[n] : 1.0f;

    cpsh(s_w, W0, 2 * KP * FF, tid, 256);
    cpsh(s_b, b0, FF, tid, 256);
    __syncthreads();

    int isV = tid >> 7;
    if (n >= NN) return;

    float inv = 1.0f / fmaxf(cnt, 1.0f);
    const float* ws = s_w + (isV ? KP * FF : 0);

    V32 acc;
    if (isV) {
#pragma unroll
        for (int j = 0; j < FF; j++) acc.f[j] = 0.f;
    } else {
        ldbias(acc, s_b);
    }

    const float* xpa = acca + (size_t)n * FF;
#pragma unroll
    for (int k4 = 0; k4 < 8; k4++) {
        float4 xv = *(const float4*)(xpa + k4 * 4);
        xv.x = fmaxf(xv.x, 0.f) * inv;
        xv.y = fmaxf(xv.y, 0.f) * inv;
        xv.z = fmaxf(xv.z, 0.f) * inv;
        xv.w = fmaxf(xv.w, 0.f) * inv;
        int k = k4 * 4;
        fmarow1(acc, pk2(xv.x), ws + (k + 0) * FF);
        fmarow1(acc, pk2(xv.y), ws + (k + 1) * FF);
        fmarow1(acc, pk2(xv.z), ws + (k + 2) * FF);
        fmarow1(acc, pk2(xv.w), ws + (k + 3) * FF);
    }
    if (KP == 64) {
        const float* xpb = accb + (size_t)n * FF;
#pragma unroll
        for (int k4 = 0; k4 < 8; k4++) {
            float4 xv = *(const float4*)(xpb + k4 * 4);
            xv.x = fmaxf(xv.x, 0.f) * inv;
            xv.y = fmaxf(xv.y, 0.f) * inv;
            xv.z = fmaxf(xv.z, 0.f) * inv;
            xv.w = fmaxf(xv.w, 0.f) * inv;
            int k = 32 + k4 * 4;
            fmarow1(acc, pk2(xv.x), ws + (k + 0) * FF);
            fmarow1(acc, pk2(xv.y), ws + (k + 1) * FF);
            fmarow1(acc, pk2(xv.z), ws + (k + 2) * FF);
            fmarow1(acc, pk2(xv.w), ws + (k + 3) * FF);
        }
    }

    float* up = g_uv + (size_t)n * 64 + isV * 32;
#pragma unroll
    for (int j = 0; j < FF; j += 4) *(float4*)(up + j) = *(float4*)(acc.f + j);
}

// ---------------- conv1 (pair; transposed e1 store) ----------------
__global__ __launch_bounds__(128) void k_conv1(const float* __restrict__ ea,
                                               const int* __restrict__ eidx,
                                               const float* __restrict__ w10,
                                               const float* __restrict__ b10,
                                               const float* __restrict__ w11,
                                               const float* __restrict__ b11) {
    __shared__ __align__(16) float s_w0[4 * FF];
    __shared__ __align__(16) float s_b0[FF];
    __shared__ __align__(16) float s_w1[FF * FF];
    __shared__ __align__(16) float s_b1[FF];
    int tid = threadIdx.x, nt = blockDim.x;

    int p = blockIdx.x * nt + tid;
    bool act = p < HALF_E;
    int e0 = 2 * p, e1 = 2 * p + 1;
    float4 a0, a1;
    int r0 = 0, r1 = 0;
    if (act) {
        a0 = *(const float4*)(ea + (size_t)e0 * 4);
        a1 = *(const float4*)(ea + (size_t)e1 * 4);
        r0 = eidx[e0];
        r1 = eidx[e1];
    }

    cpsh(s_w0, w10, 4 * FF, tid, nt);
    cpsh(s_b0, b10, FF, tid, nt);
    cpsh(s_w1, w11, FF * FF, tid, nt);
    cpsh(s_b1, b11, FF, tid, nt);
    __syncthreads();
    if (!act) return;

    V32 h0, h1;
    ldbias(h0, s_b0);
    ldbias(h1, s_b0);
    fmarow2p(h0, h1, pk2(a0.x), pk2(a1.x), s_w0);
    fmarow2p(h0, h1, pk2(a0.y), pk2(a1.y), s_w0 + FF);
    fmarow2p(h0, h1, pk2(a0.z), pk2(a1.z), s_w0 + 2 * FF);
    fmarow2p(h0, h1, pk2(a0.w), pk2(a1.w), s_w0 + 3 * FF);
    relu32(h0);
    relu32(h1);

    V32 o0, o1;
    layer2p(o0, o1, h0, h1, s_w1, s_b1);

    scatter32(g_acc1 + (size_t)r0 * FF, o0);
    scatter32(g_acc1 + (size_t)r1 * FF, o1);
    atomicAdd(&g_cnt[r0], 1.0f);
    atomicAdd(&g_cnt[r1], 1.0f);
    store_relu2T(g_e1, e0, o0, o1);
}

// ---------------- edge2 (transposed e1 read, e2 write) ----------------
__global__ __launch_bounds__(128) void k_edge2(const float* __restrict__ ea,
                                               const int* __restrict__ eidx,
                                               const float* __restrict__ w20,
                                               const float* __restrict__ w21,
                                               const float* __restrict__ b21) {
    __shared__ __align__(16) float s_w0e[36 * FF];
    __shared__ __align__(16) float s_w1[FF * FF];
    __shared__ __align__(16) float s_b1[FF];
    int tid = threadIdx.x, nt = blockDim.x;

    int p = blockIdx.x * nt + tid;
    bool act = p < HALF_E;
    int e0 = 2 * p, e1 = 2 * p + 1;
    int r0 = 0, c0 = 0, r1 = 0, c1 = 0;
    float4 a0, a1;
    V32 h0, h1;
    if (act) {
        r0 = eidx[e0];
        c0 = eidx[EE + e0];
        r1 = eidx[e1];
        c1 = eidx[EE + e1];
        uvinit(h0, r0, c0);
        uvinit(h1, r1, c1);
        a0 = *(const float4*)(ea + (size_t)e0 * 4);
        a1 = *(const float4*)(ea + (size_t)e1 * 4);
    }

    cpsh(s_w0e, w20 + 64 * FF, 36 * FF, tid, nt);
    cpsh(s_w1, w21, FF * FF, tid, nt);
    cpsh(s_b1, b21, FF, tid, nt);
    __syncthreads();
    if (!act) return;

    fmarow2p(h0, h1, pk2(a0.x), pk2(a1.x), s_w0e);
    fmarow2p(h0, h1, pk2(a0.y), pk2(a1.y), s_w0e + FF);
    fmarow2p(h0, h1, pk2(a0.z), pk2(a1.z), s_w0e + 2 * FF);
    fmarow2p(h0, h1, pk2(a0.w), pk2(a1.w), s_w0e + 3 * FF);
    seg32pT(h0, h1, g_e1, e0, s_w0e + 4 * FF);
    relu32(h0);
    relu32(h1);

    V32 o0, o1;
    layer2p(o0, o1, h0, h1, s_w1, s_b1);

    scatter32(g_acc2 + (size_t)r0 * FF, o0);
    scatter32(g_acc2 + (size_t)r1 * FF, o1);
    store_relu2T(g_e2, e0, o0, o1);
}

// ---------------- edge3 ----------------
__global__ __launch_bounds__(128) void k_edge3(const int* __restrict__ eidx,
                                               const float* __restrict__ w30,
                                               const float* __restrict__ w31,
                                               const float* __restrict__ b31) {
    __shared__ __align__(16) float s_w0e[64 * FF];
    __shared__ __align__(16) float s_w1[FF * FF];
    __shared__ __align__(16) float s_b1[FF];
    int tid = threadIdx.x, nt = blockDim.x;

    int p = blockIdx.x * nt + tid;
    bool act = p < HALF_E;
    int e0 = 2 * p, e1 = 2 * p + 1;
    int r0 = 0, c0 = 0, r1 = 0, c1 = 0;
    V32 h0, h1;
    if (act) {
        r0 = eidx[e0];
        c0 = eidx[EE + e0];
        r1 = eidx[e1];
        c1 = eidx[EE + e1];
        uvinit(h0, r0, c0);
        uvinit(h1, r1, c1);
    }

    cpsh(s_w0e, w30 + 128 * FF, 64 * FF, tid, nt);
    cpsh(s_w1, w31, FF * FF, tid, nt);
    cpsh(s_b1, b31, FF, tid, nt);
    __syncthreads();
    if (!act) return;

    seg32pT(h0, h1, g_e2, e0, s_w0e);
    seg32pT(h0, h1, g_e1, e0, s_w0e + 32 * FF);
    relu32(h0);
    relu32(h1);

    V32 o0, o1;
    layer2p(o0, o1, h0, h1, s_w1, s_b1);

    scatter32(g_acc3 + (size_t)r0 * FF, o0);
    scatter32(g_acc3 + (size_t)r1 * FF, o1);
    store_relu2T(g_e3, e0, o0, o1);
}

// ---------------- edge4 + folded heads ----------------
__global__ __launch_bounds__(128) void k_edge4(const float* __restrict__ ea,
                                               const int* __restrict__ eidx,
                                               const float* __restrict__ w40,
                                               const float* __restrict__ w41,
                                               const float* __restrict__ b41,
                                               float* __restrict__ out) {
    __shared__ __align__(16) float s_w0e[64 * FF];
    __shared__ __align__(16) float s_w1[FF * FF];
    __shared__ __align__(16) float s_b1[FF];
    __shared__ __align__(16) float s_wx[FF * 4];
    __shared__ __align__(16) float s_wz[FF];
    __shared__ float s_bx[4];
    __shared__ float s_bz;
    int tid = threadIdx.x, nt = blockDim.x;

    int p = blockIdx.x * nt + tid;
    bool act = p < HALF_E;
    int e0 = 2 * p, e1 = 2 * p + 1;
    int r0 = 0, c0 = 0, r1 = 0, c1 = 0;
    float4 a0, a1;
    V32 h0, h1;
    if (act) {
        r0 = eidx[e0];
        c0 = eidx[EE + e0];
        r1 = eidx[e1];
        c1 = eidx[EE + e1];
        uvinit(h0, r0, c0);
        uvinit(h1, r1, c1);
        a0 = *(const float4*)(ea + (size_t)e0 * 4);
        a1 = *(const float4*)(ea + (size_t)e1 * 4);
    }

    cpsh(s_w0e, w40 + 128 * FF, 64 * FF, tid, nt);
    cpsh(s_w1, w41, FF * FF, tid, nt);
    cpsh(s_b1, b41, FF, tid, nt);
    cpsh(s_wx, g_wx, FF * 4, tid, nt);
    cpsh(s_wz, g_wz, FF, tid, nt);
    if (tid < 4) s_bx[tid] = g_bx[tid];
    if (tid == 0) s_bz = g_bz;
    __syncthreads();
    if (!act) return;

    seg32pT(h0, h1, g_e3, e0, s_w0e);
    seg32pT(h0, h1, g_e2, e0, s_w0e + 32 * FF);
    relu32(h0);
    relu32(h1);

    V32 e40, e41;
    layer2p(e40, e41, h0, h1, s_w1, s_b1);
    relu32(e40);
    relu32(e41);

    float x00 = s_bx[0] + a0.x, x01 = s_bx[1] + a0.y, x02 = s_bx[2] + a0.z,
          x03 = s_bx[3] + a0.w;
    float x10 = s_bx[0] + a1.x, x11 = s_bx[1] + a1.y, x12 = s_bx[2] + a1.z,
          x13 = s_bx[3] + a1.w;
    float z0 = s_bz, z1 = s_bz;
#pragma unroll
    for (int k = 0; k < FF; k++) {
        float4 w = *(const float4*)(s_wx + k * 4);
        float wzk = s_wz[k];
        float v0 = e40.f[k], v1 = e41.f[k];
        x00 += v0 * w.x;
        x01 += v0 * w.y;
        x02 += v0 * w.z;
        x03 += v0 * w.w;
        z0 += v0 * wzk;
        x10 += v1 * w.x;
        x11 += v1 * w.y;
        x12 += v1 * w.z;
        x13 += v1 * w.w;
        z1 += v1 * wzk;
    }
    {
        float nrm = sqrtf(x00 * x00 + x01 * x01 + x02 * x02 + x03 * x03);
        float inv = 1.0f / fmaxf(nrm, 1e-12f);
        *(float4*)(out + (size_t)EE + (size_t)e0 * 4) =
            make_float4(x00 * inv, x01 * inv, x02 * inv, x03 * inv);
    }
    {
        float nrm = sqrtf(x10 * x10 + x11 * x11 + x12 * x12 + x13 * x13);
        float inv = 1.0f / fmaxf(nrm, 1e-12f);
        *(float4*)(out + (size_t)EE + (size_t)e1 * 4) =
            make_float4(x10 * inv, x11 * inv, x12 * inv, x13 * inv);
    }
    out[e0] = 1.0f / (1.0f + expf(-z0));
    out[e1] = 1.0f / (1.0f + expf(-z1));
}

// ---------------- launch ----------------
extern "C" void kernel_launch(void* const* d_in, const int* in_sizes, int n_in,
                              void* d_out, int out_size) {
    const int* eidx = (const int*)d_in[1];
    const float* ea = (const float*)d_in[2];
    const float* beta = (const float*)d_in[3];
    const float* w10 = (const float*)d_in[4];
    const float* b10 = (const float*)d_in[5];
    const float* w11 = (const float*)d_in[6];
    const float* b11 = (const float*)d_in[7];
    const float* w20 = (const float*)d_in[8];
    const float* b20 = (const float*)d_in[9];
    const float* w21 = (const float*)d_in[10];
    const float* b21 = (const float*)d_in[11];
    const float* w30 = (const float*)d_in[12];
    const float* b30 = (const float*)d_in[13];
    const float* w31 = (const float*)d_in[14];
    const float* b31 = (const float*)d_in[15];
    const float* w40 = (const float*)d_in[16];
    const float* b40 = (const float*)d_in[17];
    const float* w41 = (const float*)d_in[18];
    const float* b41 = (const float*)d_in[19];
    const float* wl01 = (const float*)d_in[20];
    const float* bl01 = (const float*)d_in[21];
    const float* wl02 = (const float*)d_in[22];
    const float* bl02 = (const float*)d_in[23];
    const float* wl1 = (const float*)d_in[24];
    const float* bl1 = (const float*)d_in[25];
    const float* wl2 = (const float*)d_in[26];
    const float* bl2 = (const float*)d_in[27];
    float* out = (float*)d_out;

    float *acc1p, *acc2p, *acc3p;
    cudaGetSymbolAddress((void**)&acc1p, g_acc1);
    cudaGetSymbolAddress((void**)&acc2p, g_acc2);
    cudaGetSymbolAddress((void**)&acc3p, g_acc3);

    const int T = 256;
    const int gridNF = (NN * FF + T - 1) / T;
    const int TB = 128;
    const int gridP = (HALF_E + TB - 1) / TB;
    const int gridN = (NN + 127) / 128;

    k_init<<<gridNF, T>>>(beta, out);
    k_headfold<<<1, 192>>>(wl01, bl01, wl02, bl02, wl1, bl1, wl2, bl2);
    k_conv1<<<gridP, TB>>>(ea, eidx, w10, b10, w11, b11);

    k_node<32><<<gridN, 256>>>(acc1p, nullptr, w20, b20);
    k_edge2<<<gridP, TB>>>(ea, eidx, w20, w21, b21);

    k_node<64><<<gridN, 256>>>(acc2p, acc1p, w30, b30);
    k_edge3<<<gridP, TB>>>(eidx, w30, w31, b31);

    k_node<64><<<gridN, 256>>>(acc3p, acc2p, w40, b40);
    k_edge4<<<gridP, TB>>>(ea, eidx, w40, w41, b41, out);
}